// round 3
// baseline (speedup 1.0000x reference)
#include <cuda_runtime.h>
#include <math.h>

typedef unsigned long long u64;

// ---------------- constants ----------------
#define T_TOK 512
#define H_DIM 2048
#define N_EXP 32
#define N_GRP 8
#define TOPK_GRP 4
#define TOP_K 6
#define I_DIM 1408
#define I2_DIM 2816      // 2*I
#define NSI 2816         // NS*I
#define NSI2 5632        // 2*NS*I
#define SCALE_F 2.5f
#define MAXM 512
#define NPAIR (T_TOK * TOP_K)   // 3072

// ---------------- scratch (static device memory; no allocation) ----------------
__device__ float g_GU[NPAIR * I2_DIM];     // 34.6 MB  gate/up pre-activation (routed)
__device__ float g_ACT1[NPAIR * I_DIM];    // 17.3 MB  silu*up (routed)
__device__ float g_EO[NPAIR * H_DIM];      // 25.2 MB  per-pair expert output
__device__ float g_GUS[T_TOK * NSI2];      // 11.5 MB  shared gate/up
__device__ float g_ACTS[T_TOK * NSI];      //  5.8 MB  shared act
__device__ int   g_topk_ids[NPAIR];
__device__ float g_topk_w[NPAIR];
__device__ int   g_counts[N_EXP];
__device__ int   g_ex_tok[N_EXP * MAXM];
__device__ int   g_ex_pair[N_EXP * MAXM];

// ---------------- f32x2 helpers ----------------
__device__ __forceinline__ u64 fma2(u64 a, u64 b, u64 c) {
    u64 d;
    asm("fma.rn.f32x2 %0, %1, %2, %3;" : "=l"(d) : "l"(a), "l"(b), "l"(c));
    return d;
}
__device__ __forceinline__ u64 dup2(float x) {
    u64 d;
    asm("mov.b64 %0, {%1, %1};" : "=l"(d) : "f"(x));
    return d;
}
__device__ __forceinline__ float2 unpack2(u64 v) {
    float2 r;
    asm("mov.b64 {%0, %1}, %2;" : "=f"(r.x), "=f"(r.y) : "l"(v));
    return r;
}

// ---------------- router: logits + sigmoid + grouped topk ----------------
// 16 blocks x 256 threads. Each warp handles 4 tokens; lane = expert.
__global__ void __launch_bounds__(256) router_kernel(
    const float* __restrict__ x, const float* __restrict__ gw,
    const float* __restrict__ bias, int* __restrict__ ids, float* __restrict__ tw)
{
    const unsigned FULL = 0xffffffffu;
    int warp = threadIdx.x >> 5, lane = threadIdx.x & 31;
    int t0 = (blockIdx.x * 8 + warp) * 4;
    const float* xr = x + (size_t)t0 * H_DIM;
    float b = bias[lane];

    float acc0 = 0.f, acc1 = 0.f, acc2 = 0.f, acc3 = 0.f;
    #pragma unroll 4
    for (int h = 0; h < H_DIM; h++) {
        float g = gw[h * N_EXP + lane];
        acc0 += xr[h] * g;
        acc1 += xr[H_DIM + h] * g;
        acc2 += xr[2 * H_DIM + h] * g;
        acc3 += xr[3 * H_DIM + h] * g;
    }
    float logits[4] = {acc0, acc1, acc2, acc3};

    for (int tt = 0; tt < 4; tt++) {
        int t = t0 + tt;
        float s   = 1.f / (1.f + expf(-logits[tt]));  // raw sigmoid (weights)
        float sfc = s + b;                              // bias-corrected (selection)

        // --- top-2 sum within each 4-lane group ---
        float a  = sfc;
        float bb = __shfl_xor_sync(FULL, a, 1);
        float hi = fmaxf(a, bb), lo = fminf(a, bb);
        float hi2 = __shfl_xor_sync(FULL, hi, 2);
        float lo2 = __shfl_xor_sync(FULL, lo, 2);
        float top1   = fmaxf(hi, hi2);
        float second = fmaxf(fminf(hi, hi2), fmaxf(lo, lo2));
        float gscore = top1 + second;   // same in all 4 lanes of the group
        int gid = lane >> 2;

        // --- rank groups, keep top TOPK_GRP (ties -> lower index) ---
        int grank = 0;
        #pragma unroll
        for (int j = 0; j < N_GRP; j++) {
            float gj = __shfl_sync(FULL, gscore, j * 4);
            grank += (gj > gscore) || (gj == gscore && j < gid);
        }
        float masked = (grank < TOPK_GRP) ? sfc : -INFINITY;

        // --- rank experts among masked, keep TOP_K ---
        int rank = 0;
        #pragma unroll
        for (int j = 0; j < 32; j++) {
            float vj = __shfl_sync(FULL, masked, j);
            rank += (vj > masked) || (vj == masked && j < lane);
        }
        bool sel = rank < TOP_K;

        float wsum = sel ? s : 0.f;
        #pragma unroll
        for (int off = 16; off; off >>= 1) wsum += __shfl_xor_sync(FULL, wsum, off);

        if (sel) {
            ids[t * TOP_K + rank] = lane;
            tw[t * TOP_K + rank]  = s / wsum * SCALE_F;
        }
    }
}

// ---------------- deterministic expert->token compaction ----------------
// 1 block, 1024 threads; warp w = expert w; lane l scans tokens [16l, 16l+16)
__global__ void __launch_bounds__(1024) build_lists_kernel(
    const int* __restrict__ ids, int* __restrict__ counts,
    int* __restrict__ ex_tok, int* __restrict__ ex_pair)
{
    const unsigned FULL = 0xffffffffu;
    int e = threadIdx.x >> 5;
    int lane = threadIdx.x & 31;
    int t0 = lane * 16;

    int cnt = 0;
    for (int t = t0; t < t0 + 16; t++)
        #pragma unroll
        for (int k = 0; k < TOP_K; k++)
            if (ids[t * TOP_K + k] == e) cnt++;

    int off = cnt;
    #pragma unroll
    for (int d = 1; d < 32; d <<= 1) {
        int v = __shfl_up_sync(FULL, off, d);
        if (lane >= d) off += v;
    }
    int total = __shfl_sync(FULL, off, 31);
    off -= cnt;   // exclusive

    for (int t = t0; t < t0 + 16; t++)
        #pragma unroll
        for (int k = 0; k < TOP_K; k++)
            if (ids[t * TOP_K + k] == e) {
                ex_tok[e * MAXM + off]  = t;
                ex_pair[e * MAXM + off] = t * TOP_K + k;
                off++;
            }
    if (lane == 0) counts[e] = total;
}

// ---------------- generic SGEMM: C[rowC[m]] = A[rowA[m]] @ (B + e*strideB) ----------------
// 128x128 tile, BK=16, 256 threads, 8x8 micro-tile via fma.rn.f32x2 (N-paired acc).
#define BM 128
#define BN 128
#define BK 16

__global__ void __launch_bounds__(256, 2) sgemm_kernel(
    const float* __restrict__ A, const float* __restrict__ B, float* __restrict__ C,
    int Mfixed, const int* __restrict__ Mcnt,
    int K, int lda, int ldb, int ldc, size_t strideB,
    const int* __restrict__ rowsA, const int* __restrict__ rowsC)
{
    __shared__ __align__(16) float As[2][BK][BM + 4];
    __shared__ __align__(16) float Bs[2][BK][BN];

    int e = blockIdx.z;
    int M = Mcnt ? Mcnt[e] : Mfixed;
    int m0 = blockIdx.y * BM;
    if (m0 >= M) return;
    int n0 = blockIdx.x * BN;

    const float* Bb = B + (size_t)e * strideB + n0;
    const int* rA = rowsA ? rowsA + e * MAXM : nullptr;
    const int* rC = rowsC ? rowsC + e * MAXM : nullptr;

    int tid = threadIdx.x;
    // A tile load mapping: thread -> (row am, 8 consecutive k)
    int am = tid >> 1;
    int ak = (tid & 1) * 8;
    int mg = m0 + am; if (mg > M - 1) mg = M - 1;
    int arow = rA ? rA[mg] : mg;
    const float* Ag = A + (size_t)arow * lda + ak;
    // B tile load mapping: thread -> (k row bkr, 8 consecutive n)
    int bkr = tid >> 4;
    int bn  = (tid & 15) * 8;
    const float* Bg = Bb + (size_t)bkr * ldb + bn;

    int tx = tid & 15, ty = tid >> 4;

    u64 acc[8][4];
    #pragma unroll
    for (int i = 0; i < 8; i++)
        #pragma unroll
        for (int j = 0; j < 4; j++) acc[i][j] = 0ull;

    float4 a0 = *(const float4*)Ag;
    float4 a1 = *(const float4*)(Ag + 4);
    float4 b0 = *(const float4*)Bg;
    float4 b1 = *(const float4*)(Bg + 4);

    As[0][ak+0][am] = a0.x; As[0][ak+1][am] = a0.y; As[0][ak+2][am] = a0.z; As[0][ak+3][am] = a0.w;
    As[0][ak+4][am] = a1.x; As[0][ak+5][am] = a1.y; As[0][ak+6][am] = a1.z; As[0][ak+7][am] = a1.w;
    *(float4*)&Bs[0][bkr][bn]     = b0;
    *(float4*)&Bs[0][bkr][bn + 4] = b1;
    __syncthreads();

    int nk = K / BK;
    for (int kt = 0; kt < nk; kt++) {
        int buf = kt & 1;
        bool more = (kt + 1 < nk);
        if (more) {
            Ag += BK; Bg += (size_t)BK * ldb;
            a0 = *(const float4*)Ag; a1 = *(const float4*)(Ag + 4);
            b0 = *(const float4*)Bg; b1 = *(const float4*)(Bg + 4);
        }
        #pragma unroll
        for (int kk = 0; kk < BK; kk++) {
            float4 afA = *(const float4*)&As[buf][kk][ty * 8];
            float4 afB = *(const float4*)&As[buf][kk][ty * 8 + 4];
            ulonglong2 bv0 = *(const ulonglong2*)&Bs[buf][kk][tx * 8];
            ulonglong2 bv1 = *(const ulonglong2*)&Bs[buf][kk][tx * 8 + 4];
            float afr[8] = {afA.x, afA.y, afA.z, afA.w, afB.x, afB.y, afB.z, afB.w};
            #pragma unroll
            for (int i = 0; i < 8; i++) {
                u64 ad = dup2(afr[i]);
                acc[i][0] = fma2(ad, bv0.x, acc[i][0]);
                acc[i][1] = fma2(ad, bv0.y, acc[i][1]);
                acc[i][2] = fma2(ad, bv1.x, acc[i][2]);
                acc[i][3] = fma2(ad, bv1.y, acc[i][3]);
            }
        }
        if (more) {
            int nb = buf ^ 1;
            As[nb][ak+0][am] = a0.x; As[nb][ak+1][am] = a0.y; As[nb][ak+2][am] = a0.z; As[nb][ak+3][am] = a0.w;
            As[nb][ak+4][am] = a1.x; As[nb][ak+5][am] = a1.y; As[nb][ak+6][am] = a1.z; As[nb][ak+7][am] = a1.w;
            *(float4*)&Bs[nb][bkr][bn]     = b0;
            *(float4*)&Bs[nb][bkr][bn + 4] = b1;
        }
        __syncthreads();
    }

    #pragma unroll
    for (int i = 0; i < 8; i++) {
        int m = m0 + ty * 8 + i;
        if (m < M) {
            int crow = rC ? rC[m] : m;
            float* Cp = C + (size_t)crow * ldc + n0 + tx * 8;
            float2 p0 = unpack2(acc[i][0]);
            float2 p1 = unpack2(acc[i][1]);
            float2 p2 = unpack2(acc[i][2]);
            float2 p3 = unpack2(acc[i][3]);
            *(float4*)Cp       = make_float4(p0.x, p0.y, p1.x, p1.y);
            *(float4*)(Cp + 4) = make_float4(p2.x, p2.y, p3.x, p3.y);
        }
    }
}

// ---------------- silu(gate) * up ----------------
__global__ void silu_mul_kernel(const float* __restrict__ gu, float* __restrict__ out,
                                int rows, int half, int ld)
{
    int total = rows * half;
    for (int idx = blockIdx.x * blockDim.x + threadIdx.x; idx < total;
         idx += gridDim.x * blockDim.x) {
        int r = idx / half, c = idx - r * half;
        float g = gu[(size_t)r * ld + c];
        float u = gu[(size_t)r * ld + half + c];
        out[idx] = (g / (1.f + expf(-g))) * u;
    }
}

// ---------------- combine: out[t] += sum_k w[t,k] * EO[t*6+k] ----------------
__global__ void __launch_bounds__(256) combine_kernel(
    const float* __restrict__ EO, const float* __restrict__ tw, float* __restrict__ out)
{
    int t = blockIdx.x;
    const float* w = tw + t * TOP_K;
    float w0 = w[0], w1 = w[1], w2v = w[2], w3 = w[3], w4 = w[4], w5 = w[5];
    const float* eb = EO + (size_t)t * TOP_K * H_DIM;
    float* orow = out + (size_t)t * H_DIM;
    for (int c = threadIdx.x; c < H_DIM; c += blockDim.x) {
        float v = orow[c];
        v += w0  * eb[c]
           + w1  * eb[H_DIM + c]
           + w2v * eb[2 * H_DIM + c]
           + w3  * eb[3 * H_DIM + c]
           + w4  * eb[4 * H_DIM + c]
           + w5  * eb[5 * H_DIM + c];
        orow[c] = v;
    }
}

// ---------------- launch ----------------
extern "C" void kernel_launch(void* const* d_in, const int* in_sizes, int n_in,
                              void* d_out, int out_size)
{
    (void)in_sizes; (void)n_in; (void)out_size;
    const float* x      = (const float*)d_in[0];
    // d_in[1] residual: unused by reference output
    const float* gate_w = (const float*)d_in[2];
    const float* cbias  = (const float*)d_in[3];
    const float* w13    = (const float*)d_in[4];
    const float* w2     = (const float*)d_in[5];
    const float* swgu   = (const float*)d_in[6];
    const float* swdn   = (const float*)d_in[7];
    float* out = (float*)d_out;

    float *pGU, *pACT1, *pEO, *pGUS, *pACTS, *ptw;
    int *pids, *pcnt, *ptok, *ppair;
    cudaGetSymbolAddress((void**)&pGU,   g_GU);
    cudaGetSymbolAddress((void**)&pACT1, g_ACT1);
    cudaGetSymbolAddress((void**)&pEO,   g_EO);
    cudaGetSymbolAddress((void**)&pGUS,  g_GUS);
    cudaGetSymbolAddress((void**)&pACTS, g_ACTS);
    cudaGetSymbolAddress((void**)&ptw,   g_topk_w);
    cudaGetSymbolAddress((void**)&pids,  g_topk_ids);
    cudaGetSymbolAddress((void**)&pcnt,  g_counts);
    cudaGetSymbolAddress((void**)&ptok,  g_ex_tok);
    cudaGetSymbolAddress((void**)&ppair, g_ex_pair);

    // 1) router + topk
    router_kernel<<<16, 256>>>(x, gate_w, cbias, pids, ptw);
    // 2) deterministic per-expert lists
    build_lists_kernel<<<1, 1024>>>(pids, pcnt, ptok, ppair);
    // 3) routed gate/up: GU[pair] = x[tok] @ w13[e]   (K=2048, N=2816)
    sgemm_kernel<<<dim3(I2_DIM / BN, T_TOK / BM, N_EXP), 256>>>(
        x, w13, pGU, 0, pcnt, H_DIM, H_DIM, I2_DIM, I2_DIM,
        (size_t)H_DIM * I2_DIM, ptok, ppair);
    // 4) silu*up
    silu_mul_kernel<<<2048, 256>>>(pGU, pACT1, NPAIR, I_DIM, I2_DIM);
    // 5) routed down: EO[pair] = ACT1[pair] @ w2[e]   (K=1408, N=2048)
    sgemm_kernel<<<dim3(H_DIM / BN, T_TOK / BM, N_EXP), 256>>>(
        pACT1, w2, pEO, 0, pcnt, I_DIM, I_DIM, H_DIM, H_DIM,
        (size_t)I_DIM * H_DIM, ppair, ppair);
    // 6) shared gate/up: GUS = x @ shared_w_gu        (K=2048, N=5632)
    sgemm_kernel<<<dim3(NSI2 / BN, T_TOK / BM, 1), 256>>>(
        x, swgu, pGUS, T_TOK, nullptr, H_DIM, H_DIM, NSI2, NSI2,
        0, nullptr, nullptr);
    // 7) shared silu*up
    silu_mul_kernel<<<1024, 256>>>(pGUS, pACTS, T_TOK, NSI, NSI2);
    // 8) shared down -> d_out (writes every element)
    sgemm_kernel<<<dim3(H_DIM / BN, T_TOK / BM, 1), 256>>>(
        pACTS, swdn, out, T_TOK, nullptr, NSI, NSI, H_DIM, H_DIM,
        0, nullptr, nullptr);
    // 9) out += weighted routed expert outputs (deterministic order)
    combine_kernel<<<T_TOK, 256>>>(pEO, ptw, out);
}